// round 8
// baseline (speedup 1.0000x reference)
#include <cuda_runtime.h>
#include <math.h>

#define BMAX 2048

// ---------------- device scratch (no allocations allowed) ----------------
__device__ float g_rel[256];            // 16x16 isometry
__device__ float g_W[256];              // expm(-sym(bias_spd)/2)
__device__ float g_Ybg[400];            // cayley(bias_gr) 20x20
__device__ float g_X[2][BMAX][256];     // SPD chain results (0=q,1=a)
__device__ float g_C[2][BMAX][200];     // GR 20x10 panels   (0=q,1=a)

// =====================================================================
// Kernel 0: one-block precompute of batch-invariant matrices
// =====================================================================
__global__ void precompute_kernel(const float* __restrict__ ref_params,
                                  const float* __restrict__ bias_spd,
                                  const float* __restrict__ bias_gr)
{
    __shared__ float Bs[256], E[256];
    __shared__ float A20[400];
    __shared__ float Aug[20][40];
    __shared__ float prow[40], fcol[20];
    __shared__ float pv;

    const int tid = threadIdx.x;
    const int i = tid >> 4, j = tid & 15;

    // ---- rel = prod of 120 Givens rotations, each lane owns one row ----
    if (tid < 16) {
        float row[16];
        #pragma unroll
        for (int c = 0; c < 16; c++) row[c] = (c == tid) ? 1.f : 0.f;
        int m = 0;
        for (int pi = 0; pi < 16; pi++) {
            for (int pj = pi + 1; pj < 16; pj++) {
                float ang = ref_params[m++];
                float c = cosf(ang), s = sinf(ang);
                float a = row[pi], b = row[pj];
                row[pi] = c * a + s * b;
                row[pj] = -s * a + c * b;
            }
        }
        #pragma unroll
        for (int c = 0; c < 16; c++) g_rel[tid * 16 + c] = row[c];
    }

    // ---- W = expm(-0.25*(bias+bias^T)) via scaling(2^-7) + Taylor-8 ----
    {
        float v = -0.25f * (bias_spd[i * 16 + j] + bias_spd[j * 16 + i]);
        Bs[tid] = v * (1.0f / 128.0f);
        E[tid]  = (i == j) ? 1.f : 0.f;
    }
    __syncthreads();
    for (int k = 8; k >= 1; k--) {
        float a = 0.f;
        #pragma unroll
        for (int kk = 0; kk < 16; kk++) a += Bs[i * 16 + kk] * E[kk * 16 + j];
        __syncthreads();
        E[tid] = ((i == j) ? 1.f : 0.f) + a * (1.0f / (float)k);
        __syncthreads();
    }
    for (int q = 0; q < 7; q++) {
        float a = 0.f;
        #pragma unroll
        for (int kk = 0; kk < 16; kk++) a += E[i * 16 + kk] * E[kk * 16 + j];
        __syncthreads();
        E[tid] = a;
        __syncthreads();
    }
    g_W[tid] = E[tid];

    // ---- Ybg = (I - A)(I + A)^{-1}, A = skew(bias_gr) 20x20 ----
    for (int e = tid; e < 400; e += 256) {
        int ii = e / 20, jj = e % 20;
        float v = 0.f;
        if (ii < 10 && jj >= 10)      v =  bias_gr[ii * 10 + (jj - 10)];
        else if (ii >= 10 && jj < 10) v = -bias_gr[jj * 10 + (ii - 10)];
        A20[e] = v;
    }
    __syncthreads();
    for (int e = tid; e < 800; e += 256) {
        int ii = e / 40, jj = e % 40;
        float v;
        if (jj < 20) v = ((ii == jj) ? 1.f : 0.f) + A20[ii * 20 + jj];
        else         v = ((jj - 20) == ii) ? 1.f : 0.f;
        Aug[ii][jj] = v;
    }
    __syncthreads();
    for (int p = 0; p < 20; p++) {
        if (tid == 0) pv = Aug[p][p];
        __syncthreads();
        if (tid < 40) prow[tid] = Aug[p][tid] / pv;
        if (tid >= 64 && tid < 84) {
            int r = tid - 64;
            fcol[r] = (r == p) ? 0.f : Aug[r][p];
        }
        __syncthreads();
        for (int e = tid; e < 800; e += 256) {
            int ii = e / 40, jj = e % 40;
            Aug[ii][jj] = (ii == p) ? prow[jj] : Aug[ii][jj] - fcol[ii] * prow[jj];
        }
        __syncthreads();
    }
    for (int e = tid; e < 400; e += 256) {
        int ii = e / 20, jj = e % 20;
        float a = 0.f;
        #pragma unroll
        for (int k = 0; k < 20; k++) {
            float l = ((ii == k) ? 1.f : 0.f) - A20[ii * 20 + k];
            a += l * Aug[k][jj + 20];
        }
        g_Ybg[e] = a;
    }
}

// =====================================================================
// Kernel 1: SPD chains. grid (B, 2). Y = P * exp(x_last) * P^T
// =====================================================================
__global__ void spd_chain_kernel(const int* __restrict__ q_ids,
                                 const int* __restrict__ a_ids,
                                 const float* __restrict__ q_emb,
                                 const float* __restrict__ a_emb,
                                 int T)
{
    __shared__ float Es[256], As[256], A2[256], Sm[256], P[256], T1[256];
    const int b = blockIdx.x, table = blockIdx.y;
    const int* ids = table ? a_ids : q_ids;
    const float* emb = table ? a_emb : q_emb;
    const int tid = threadIdx.x;
    const int i = tid >> 4, j = tid & 15;

    for (int t = 0; t < T; t++) {
        int id = ids[b * T + t];
        Es[tid] = emb[(size_t)id * 256 + tid];
        __syncthreads();
        float scale = (t == T - 1) ? 0.5f : 0.25f; // sym()*1 or sym()*0.5
        As[tid] = scale * (Es[tid] + Es[j * 16 + i]);
        __syncthreads();
        float a2 = 0.f;
        #pragma unroll
        for (int k = 0; k < 16; k++) a2 += As[i * 16 + k] * As[k * 16 + j];
        A2[tid] = a2;
        __syncthreads();
        float a3 = 0.f;
        #pragma unroll
        for (int k = 0; k < 16; k++) a3 += A2[i * 16 + k] * As[k * 16 + j];
        Sm[tid] = ((i == j) ? 1.f : 0.f) + As[tid] + 0.5f * a2 + (1.0f / 6.0f) * a3;
        __syncthreads();

        if (t == 0) {
            P[tid] = Sm[tid];
            __syncthreads();
        } else if (t < T - 1) {
            float acc = 0.f;
            #pragma unroll
            for (int k = 0; k < 16; k++) acc += P[i * 16 + k] * Sm[k * 16 + j];
            __syncthreads();
            P[tid] = acc;
            __syncthreads();
        } else {
            float acc = 0.f;
            #pragma unroll
            for (int k = 0; k < 16; k++) acc += P[i * 16 + k] * Sm[k * 16 + j];
            T1[tid] = acc;
            __syncthreads();
            float y = 0.f;
            #pragma unroll
            for (int k = 0; k < 16; k++) y += T1[i * 16 + k] * P[j * 16 + k]; // * P^T
            g_X[table][b][tid] = y;
        }
    }
}

// =====================================================================
// Kernel 2: Grassmannian 20x10 panel chains. grid (B, 2), 128 threads.
//   apply y_t = I - 2A + 2A^2 - 2A^3 (block form) right-to-left.
// =====================================================================
__global__ void gr_chain_kernel(const int* __restrict__ q_ids,
                                const int* __restrict__ a_ids,
                                const float* __restrict__ q_emb,
                                const float* __restrict__ a_emb,
                                const float* __restrict__ trans,
                                int T)
{
    __shared__ float x[100], Mt[100], Mb[100], u[100], v[100], p[100], q2[100], w1[100], w2[100];
    const int b = blockIdx.x, table = blockIdx.y;
    const int* ids = table ? a_ids : q_ids;
    const float* emb = table ? a_emb : q_emb;
    const int tid = threadIdx.x;
    const int i = tid / 10, j = tid % 10;

    if (tid < 100) { Mt[tid] = (i == j) ? 1.f : 0.f; Mb[tid] = 0.f; }
    __syncthreads();

    for (int t = T - 1; t >= 0; t--) {
        int id = ids[b * T + t];
        if (tid < 100) {
            float e = emb[(size_t)id * 100 + tid];
            x[tid] = table ? e : trans[tid] * e;
        }
        __syncthreads();
        if (tid < 100) {
            float su = 0.f, sv = 0.f;
            #pragma unroll
            for (int k = 0; k < 10; k++) {
                su += x[i * 10 + k] * Mb[k * 10 + j];   // u = x @ Mb
                sv += x[k * 10 + i] * Mt[k * 10 + j];   // v = x^T @ Mt
            }
            u[tid] = su; v[tid] = sv;
        }
        __syncthreads();
        if (tid < 100) {
            float sp = 0.f, sq = 0.f;
            #pragma unroll
            for (int k = 0; k < 10; k++) {
                sp += x[k * 10 + i] * u[k * 10 + j];    // p = x^T @ u
                sq += x[i * 10 + k] * v[k * 10 + j];    // q2 = x @ v
            }
            p[tid] = sp; q2[tid] = sq;
        }
        __syncthreads();
        if (tid < 100) {
            float sw1 = 0.f, sw2 = 0.f;
            #pragma unroll
            for (int k = 0; k < 10; k++) {
                sw1 += x[i * 10 + k] * (v[k * 10 + j] - p[k * 10 + j]);  // x@(v-p)
                sw2 += x[k * 10 + i] * (u[k * 10 + j] + q2[k * 10 + j]); // x^T@(u+q2)
            }
            w1[tid] = sw1; w2[tid] = sw2;
        }
        __syncthreads();
        if (tid < 100) {
            Mt[tid] = Mt[tid] - 2.f * u[tid] - 2.f * w1[tid];
            Mb[tid] = Mb[tid] + 2.f * v[tid] - 2.f * w2[tid];
        }
        __syncthreads();
    }
    if (tid < 100) {
        g_C[table][b][tid]       = Mt[tid]; // rows 0..9
        g_C[table][b][100 + tid] = Mb[tid]; // rows 10..19
    }
}

// =====================================================================
// Kernel 3: per-B finalize: rel-conj, Newton-Schulz inv-sqrt, Jacobi
// eigenvalues, Grassmannian distance, combine.
// =====================================================================
__global__ void finalize_kernel(float* __restrict__ out,
                                const float* __restrict__ wf,
                                const float* __restrict__ wb)
{
    __shared__ float B0[256], B1[256], B2[256], B3[256], B4[256], Wc[256];
    __shared__ float Ybg[400], Cq[200], Ca[200], Q1[200], sq[100], red[16];
    __shared__ int   part[16];
    __shared__ float cj[16], bj[16];
    __shared__ float dspd_sh;

    const int b = blockIdx.x, tid = threadIdx.x;
    const int i = tid >> 4, j = tid & 15;

    // ---- load ----
    B0[tid] = g_X[0][b][tid];   // Xq
    B1[tid] = g_rel[tid];
    Wc[tid] = g_W[tid];
    for (int e = tid; e < 400; e += 256) Ybg[e] = g_Ybg[e];
    if (tid < 200) { Cq[tid] = g_C[0][b][tid]; Ca[tid] = g_C[1][b][tid]; }
    __syncthreads();

    // ---- X = rel @ Xq @ rel^T ----
    float acc = 0.f;
    #pragma unroll
    for (int k = 0; k < 16; k++) acc += B1[i * 16 + k] * B0[k * 16 + j];
    B2[tid] = acc;
    __syncthreads();
    acc = 0.f;
    #pragma unroll
    for (int k = 0; k < 16; k++) acc += B2[i * 16 + k] * B1[j * 16 + k];
    __syncthreads();
    B2[tid] = acc;                       // Y0 = X
    B3[tid] = (i == j) ? 1.f : 0.f;      // Z0 = I
    __syncthreads();

    // ---- Newton-Schulz: Z -> X^{-1/2} ----
    for (int it = 0; it < 7; it++) {
        float t = 0.f;
        #pragma unroll
        for (int k = 0; k < 16; k++) t += B3[i * 16 + k] * B2[k * 16 + j]; // Z@Y
        __syncthreads();
        B4[tid] = ((i == j) ? 1.5f : 0.f) - 0.5f * t;                      // G
        __syncthreads();
        float yn = 0.f, zn = 0.f;
        #pragma unroll
        for (int k = 0; k < 16; k++) {
            yn += B2[i * 16 + k] * B4[k * 16 + j];   // Y@G
            zn += B4[i * 16 + k] * B3[k * 16 + j];   // G@Z
        }
        __syncthreads();
        B2[tid] = yn; B3[tid] = zn;
        __syncthreads();
    }

    // ---- m = W @ (Z @ Xa @ Z) @ W ----
    B0[tid] = g_X[1][b][tid];            // Xa
    __syncthreads();
    acc = 0.f;
    #pragma unroll
    for (int k = 0; k < 16; k++) acc += B3[i * 16 + k] * B0[k * 16 + j];
    B1[tid] = acc; __syncthreads();
    acc = 0.f;
    #pragma unroll
    for (int k = 0; k < 16; k++) acc += B1[i * 16 + k] * B3[k * 16 + j];
    B2[tid] = acc; __syncthreads();
    acc = 0.f;
    #pragma unroll
    for (int k = 0; k < 16; k++) acc += Wc[i * 16 + k] * B2[k * 16 + j];
    B1[tid] = acc; __syncthreads();
    acc = 0.f;
    #pragma unroll
    for (int k = 0; k < 16; k++) acc += B1[i * 16 + k] * Wc[k * 16 + j];
    __syncthreads();
    B0[tid] = acc;                       // m
    __syncthreads();

    // ---- parallel Jacobi eigenvalues (values only) ----
    for (int sweep = 0; sweep < 10; sweep++) {
        for (int r = 0; r < 15; r++) {
            if (tid < 8) {
                int pI, qI;
                if (tid == 0) { pI = 0; qI = 1 + ((14 + r) % 15); }
                else { pI = 1 + ((tid - 1 + r) % 15); qI = 1 + ((14 - tid + r) % 15); }
                float app = B0[pI * 16 + pI], aqq = B0[qI * 16 + qI], apq = B0[pI * 16 + qI];
                float c, s;
                if (fabsf(apq) < 1e-30f) { c = 1.f; s = 0.f; }
                else {
                    float tau = (aqq - app) / (2.f * apq);
                    float tt = (tau >= 0.f ? 1.f : -1.f) / (fabsf(tau) + sqrtf(1.f + tau * tau));
                    c = 1.0f / sqrtf(1.f + tt * tt); s = tt * c;
                }
                part[pI] = qI; part[qI] = pI;
                cj[pI] = c; cj[qI] = c;
                bj[pI] = -s; bj[qI] = s;
            }
            __syncthreads();
            float bv = cj[j] * B0[i * 16 + j] + bj[j] * B0[i * 16 + part[j]];
            B1[tid] = bv;
            __syncthreads();
            float av = cj[i] * B1[tid] + bj[i] * B1[part[i] * 16 + j];
            __syncthreads();
            B0[tid] = av;
            __syncthreads();
        }
    }
    if (tid < 16) {
        float d = B0[tid * 16 + tid];
        float l = logf(fmaxf(d, 1e-30f));
        red[tid] = l * l;
    }
    __syncthreads();
    if (tid == 0) {
        float s2 = 0.f;
        #pragma unroll
        for (int e = 0; e < 16; e++) s2 += red[e];
        dspd_sh = sqrtf(s2);
    }

    // ---- Grassmannian: Q1 = Ybg @ Cq ; s = ||Q1^T Ca||_F^2 ----
    if (tid < 200) {
        int ii = tid / 10, jj = tid % 10;
        float a = 0.f;
        #pragma unroll
        for (int k = 0; k < 20; k++) a += Ybg[ii * 20 + k] * Cq[k * 10 + jj];
        Q1[tid] = a;
    }
    __syncthreads();
    if (tid < 100) {
        int ii = tid / 10, jj = tid % 10;
        float a = 0.f;
        #pragma unroll
        for (int k = 0; k < 20; k++) a += Q1[k * 10 + ii] * Ca[k * 10 + jj];
        sq[tid] = a * a;
    }
    __syncthreads();
    if (tid == 0) {
        float s = 0.f;
        for (int e = 0; e < 100; e++) s += sq[e];
        float d_gr = sqrtf(fmaxf(20.f - 2.f * s, 0.f));
        out[b] = -wf[0] * (dspd_sh + d_gr) + wb[0];
    }
}

// =====================================================================
extern "C" void kernel_launch(void* const* d_in, const int* in_sizes, int n_in,
                              void* d_out, int out_size)
{
    const int*   q_ids      = (const int*)  d_in[0];
    const int*   a_ids      = (const int*)  d_in[1];
    const float* q_emb_spd  = (const float*)d_in[2];
    const float* a_emb_spd  = (const float*)d_in[3];
    const float* ref_params = (const float*)d_in[4];
    const float* bias_spd   = (const float*)d_in[5];
    const float* q_emb_gr   = (const float*)d_in[6];
    const float* a_emb_gr   = (const float*)d_in[7];
    const float* trans_gr   = (const float*)d_in[8];
    const float* bias_gr    = (const float*)d_in[9];
    const float* wf         = (const float*)d_in[10];
    const float* wb         = (const float*)d_in[11];
    float* out = (float*)d_out;

    int B = out_size;
    if (B > BMAX) B = BMAX;
    int T = in_sizes[0] / B;

    precompute_kernel<<<1, 256>>>(ref_params, bias_spd, bias_gr);
    spd_chain_kernel<<<dim3(B, 2), 256>>>(q_ids, a_ids, q_emb_spd, a_emb_spd, T);
    gr_chain_kernel<<<dim3(B, 2), 128>>>(q_ids, a_ids, q_emb_gr, a_emb_gr, trans_gr, T);
    finalize_kernel<<<B, 256>>>(out, wf, wb);
}